// round 9
// baseline (speedup 1.0000x reference)
#include <cuda_runtime.h>
#include <cuda_bf16.h>
#include <math.h>
#include <stdint.h>

// Problem constants
#define B_   2
#define T_   2048
#define C_   1024
#define H_   16
#define M_   (B_ * T_)      // 4096
#define N3C_ (3 * C_)       // 3072
#define KP_  (3 * C_)       // K' = 3*K (triple split)

// ---------------------------------------------------------------------------
// Helpers
// ---------------------------------------------------------------------------
__device__ __forceinline__ uint32_t smem_u32(const void* p) {
    uint32_t a;
    asm("{ .reg .u64 t; cvta.to.shared.u64 t, %1; cvt.u32.u64 %0, t; }"
        : "=r"(a) : "l"(p));
    return a;
}

__device__ __forceinline__ void ldsm_x4(uint32_t (&r)[4], uint32_t addr) {
    asm volatile("ldmatrix.sync.aligned.m8n8.x4.shared.b16 {%0,%1,%2,%3}, [%4];"
                 : "=r"(r[0]), "=r"(r[1]), "=r"(r[2]), "=r"(r[3]) : "r"(addr));
}

__device__ __forceinline__ void ldsm_x4_t(uint32_t (&r)[4], uint32_t addr) {
    asm volatile("ldmatrix.sync.aligned.m8n8.x4.trans.shared.b16 {%0,%1,%2,%3}, [%4];"
                 : "=r"(r[0]), "=r"(r[1]), "=r"(r[2]), "=r"(r[3]) : "r"(addr));
}

__device__ __forceinline__ void mma_bf16(float (&c)[4], const uint32_t (&a)[4],
                                         uint32_t b0, uint32_t b1) {
    asm volatile(
        "mma.sync.aligned.m16n8k16.row.col.f32.bf16.bf16.f32 "
        "{%0,%1,%2,%3}, {%4,%5,%6,%7}, {%8,%9}, {%0,%1,%2,%3};"
        : "+f"(c[0]), "+f"(c[1]), "+f"(c[2]), "+f"(c[3])
        : "r"(a[0]), "r"(a[1]), "r"(a[2]), "r"(a[3]), "r"(b0), "r"(b1));
}

__device__ __forceinline__ uint32_t packbf(float lo, float hi) {
    uint32_t u;
    asm("cvt.rn.bf16x2.f32 %0, %1, %2;" : "=r"(u) : "f"(hi), "f"(lo));
    return u;
}

__device__ __forceinline__ void cp16(uint32_t dst, const void* src) {
    asm volatile("cp.async.cg.shared.global [%0], [%1], 16;"
                 :: "r"(dst), "l"(src) : "memory");
}
#define CP_COMMIT() asm volatile("cp.async.commit_group;" ::: "memory")
#define CP_WAIT1()  asm volatile("cp.async.wait_group 1;" ::: "memory")
#define CP_WAIT0()  asm volatile("cp.async.wait_group 0;" ::: "memory")

// ---------------------------------------------------------------------------
// Scratch (device globals)
// ---------------------------------------------------------------------------
__device__ __nv_bfloat16 g_x2[(size_t)M_ * KP_];     // [Ah|Al|Ah] of x
__device__ __nv_bfloat16 g_y2[(size_t)M_ * KP_];     // [Ah|Al|Ah] of attn out
__device__ __nv_bfloat16 g_wa2[(size_t)N3C_ * KP_];  // [Bh|Bh|Bl] of snap(w_attn)
__device__ __nv_bfloat16 g_wp2[(size_t)C_ * KP_];    // [Bh|Bh|Bl] of snap(w_proj)
__device__ __nv_bfloat16 g_qkvh[(size_t)M_ * N3C_];  // qkv hi
__device__ __nv_bfloat16 g_qkvl[(size_t)M_ * N3C_];  // qkv lo
__device__ unsigned int g_maxbits[2];

// ---------------------------------------------------------------------------
// Snap + convert
// ---------------------------------------------------------------------------
__global__ void zero_scales_kernel() { g_maxbits[0] = 0u; g_maxbits[1] = 0u; }

__global__ void __launch_bounds__(256) maxabs_kernel(const float4* __restrict__ w,
                                                     int n4, int slot) {
    float m = 0.0f;
    for (int i = blockIdx.x * blockDim.x + threadIdx.x; i < n4;
         i += gridDim.x * blockDim.x) {
        float4 v = w[i];
        m = fmaxf(m, fmaxf(fmaxf(fabsf(v.x), fabsf(v.y)),
                           fmaxf(fabsf(v.z), fabsf(v.w))));
    }
    #pragma unroll
    for (int o = 16; o > 0; o >>= 1)
        m = fmaxf(m, __shfl_xor_sync(0xffffffffu, m, o));
    __shared__ float sm[8];
    int lane = threadIdx.x & 31, wd = threadIdx.x >> 5;
    if (lane == 0) sm[wd] = m;
    __syncthreads();
    if (threadIdx.x < 8) {
        m = sm[threadIdx.x];
        #pragma unroll
        for (int o = 4; o > 0; o >>= 1)
            m = fmaxf(m, __shfl_xor_sync(0xffu, m, o));
        if (threadIdx.x == 0)
            atomicMax(&g_maxbits[slot], __float_as_uint(m));
    }
}

// nearest-LUT via midpoint thresholds (equivalent to argmin over the 16-entry LUT)
__device__ __forceinline__ float snapv(float wn) {
    float a = fabsf(wn);
    float v;
    if (a < 0.11688312f) {
        if (a < 0.03846150f) v = 0.0f;
        else v = (a < 0.08391600f) ? 0.076923f : 0.090909f;
    } else if (a < 0.26666650f) {
        v = (a < 0.17142850f) ? 0.142857f : 0.2f;
    } else if (a < 0.41666650f) {
        v = 0.333333f;
    } else {
        v = (a < 0.75f) ? 0.5f : 1.0f;
    }
    return copysignf(v, wn);
}

// snap weights -> triple [hi | hi | lo], vectorized x4
__global__ void __launch_bounds__(256) snap_tc_kernel(const float4* __restrict__ w,
                                                      __nv_bfloat16* __restrict__ out,
                                                      int n4, int slot) {
    const float scale = __uint_as_float(g_maxbits[slot]) + 1e-6f;
    const float inv = 1.0f / scale;
    for (int i = blockIdx.x * blockDim.x + threadIdx.x; i < n4;
         i += gridDim.x * blockDim.x) {
        float4 wv = w[i];
        float v0 = snapv(wv.x * inv) * scale;
        float v1 = snapv(wv.y * inv) * scale;
        float v2 = snapv(wv.z * inv) * scale;
        float v3 = snapv(wv.w * inv) * scale;
        uint32_t hp0 = packbf(v0, v1), hp1 = packbf(v2, v3);
        __nv_bfloat16 h0 = __float2bfloat16(v0), h1 = __float2bfloat16(v1);
        __nv_bfloat16 h2 = __float2bfloat16(v2), h3 = __float2bfloat16(v3);
        uint32_t lp0 = packbf(v0 - __bfloat162float(h0), v1 - __bfloat162float(h1));
        uint32_t lp1 = packbf(v2 - __bfloat162float(h2), v3 - __bfloat162float(h3));
        int r = i >> 8, k = (i & 255) << 2;
        size_t base = (size_t)r * KP_;
        uint2 hp = make_uint2(hp0, hp1), lp = make_uint2(lp0, lp1);
        *(uint2*)(out + base + k)        = hp;
        *(uint2*)(out + base + 1024 + k) = hp;
        *(uint2*)(out + base + 2048 + k) = lp;
    }
}

// activations -> triple [hi | lo | hi], vectorized x4
__global__ void __launch_bounds__(256) cvt_act_kernel(const float4* __restrict__ a,
                                                      __nv_bfloat16* __restrict__ out,
                                                      int n4) {
    for (int i = blockIdx.x * blockDim.x + threadIdx.x; i < n4;
         i += gridDim.x * blockDim.x) {
        float4 v = a[i];
        uint32_t hp0 = packbf(v.x, v.y), hp1 = packbf(v.z, v.w);
        __nv_bfloat16 h0 = __float2bfloat16(v.x), h1 = __float2bfloat16(v.y);
        __nv_bfloat16 h2 = __float2bfloat16(v.z), h3 = __float2bfloat16(v.w);
        uint32_t lp0 = packbf(v.x - __bfloat162float(h0), v.y - __bfloat162float(h1));
        uint32_t lp1 = packbf(v.z - __bfloat162float(h2), v.w - __bfloat162float(h3));
        int r = i >> 8, k = (i & 255) << 2;
        size_t base = (size_t)r * KP_;
        uint2 hp = make_uint2(hp0, hp1), lp = make_uint2(lp0, lp1);
        *(uint2*)(out + base + k)        = hp;
        *(uint2*)(out + base + 1024 + k) = lp;
        *(uint2*)(out + base + 2048 + k) = hp;
    }
}

// ---------------------------------------------------------------------------
// bf16 mma.sync GEMM, cp.async 3-stage pipeline, BK=64.
// 128x128 tile, 8 warps (2m x 4n). SPLIT=1: bf16 hi/lo out; SPLIT=0: fp32 out.
// ---------------------------------------------------------------------------
#define GSTAGE_ 36864               // A(128x144) + B(128x144) bytes
#define GEMM_SMEM (3 * GSTAGE_)     // 110592
#define GNITER 48                   // 3072 / 64

template <int SPLIT>
__global__ void __launch_bounds__(256, 2)
gemm_mma(const __nv_bfloat16* __restrict__ A2, const __nv_bfloat16* __restrict__ B2,
         const float* __restrict__ bias, float* __restrict__ Cf,
         __nv_bfloat16* __restrict__ Chi, __nv_bfloat16* __restrict__ Clo, int Nd)
{
    extern __shared__ char gsm[];
    const uint32_t base = smem_u32(gsm);
    const int tid = threadIdx.x, lane = tid & 31, wid = tid >> 5;
    const int wm = wid >> 2, wn = wid & 3;
    const int m0 = blockIdx.y * 128, n0 = blockIdx.x * 128;

    // loader mapping: 2 threads per row, 4x16B chunks each
    const int lr = tid >> 1;
    const int lc = (tid & 1) * 4;
    const __nv_bfloat16* gA = A2 + (size_t)(m0 + lr) * KP_ + lc * 8;
    const __nv_bfloat16* gB = B2 + (size_t)(n0 + lr) * KP_ + lc * 8;
    const uint32_t sAo = (uint32_t)(lr * 144 + lc * 16);

    const uint32_t aoff = (uint32_t)((wm * 64 + (lane & 15)) * 144 + (lane >> 4) * 16);
    const uint32_t boff = (uint32_t)((wn * 32 + (lane & 7) + ((lane >> 4) & 1) * 8) * 144
                                     + ((lane >> 3) & 1) * 16);

    float acc[4][4][4] = {};

    // preload stages 0,1
    #pragma unroll
    for (int st = 0; st < 2; ++st) {
        const uint32_t sb = base + st * GSTAGE_;
        #pragma unroll
        for (int c = 0; c < 4; ++c) {
            cp16(sb + sAo + c * 16,         gA + st * 64 + c * 8);
            cp16(sb + 18432 + sAo + c * 16, gB + st * 64 + c * 8);
        }
        CP_COMMIT();
    }

    for (int it = 0; it < GNITER; ++it) {
        if (it + 1 < GNITER) { CP_WAIT1(); } else { CP_WAIT0(); }
        __syncthreads();
        if (it + 2 < GNITER) {
            const int st = it + 2;
            const uint32_t sb = base + (st % 3) * GSTAGE_;
            #pragma unroll
            for (int c = 0; c < 4; ++c) {
                cp16(sb + sAo + c * 16,         gA + st * 64 + c * 8);
                cp16(sb + 18432 + sAo + c * 16, gB + st * 64 + c * 8);
            }
            CP_COMMIT();
        }
        const uint32_t bA = base + (it % 3) * GSTAGE_;
        const uint32_t bB = bA + 18432;
        #pragma unroll
        for (int ks = 0; ks < 4; ++ks) {
            uint32_t af[4][4];
            #pragma unroll
            for (int mt = 0; mt < 4; ++mt)
                ldsm_x4(af[mt], bA + aoff + mt * (16 * 144) + ks * 32);
            #pragma unroll
            for (int p = 0; p < 2; ++p) {
                uint32_t bf[4];
                ldsm_x4(bf, bB + boff + p * (16 * 144) + ks * 32);
                #pragma unroll
                for (int mt = 0; mt < 4; ++mt) {
                    mma_bf16(acc[mt][2 * p],     af[mt], bf[0], bf[1]);
                    mma_bf16(acc[mt][2 * p + 1], af[mt], bf[2], bf[3]);
                }
            }
        }
    }

    #pragma unroll
    for (int nt = 0; nt < 4; ++nt) {
        const int col = n0 + wn * 32 + nt * 8 + (lane & 3) * 2;
        const float bv0 = bias[col];
        const float bv1 = bias[col + 1];
        #pragma unroll
        for (int mt = 0; mt < 4; ++mt) {
            const int row = m0 + wm * 64 + mt * 16 + (lane >> 2);
            float v0 = acc[mt][nt][0] + bv0, v1 = acc[mt][nt][1] + bv1;
            float v2 = acc[mt][nt][2] + bv0, v3 = acc[mt][nt][3] + bv1;
            if (SPLIT) {
                __nv_bfloat16 h0 = __float2bfloat16(v0), h1 = __float2bfloat16(v1);
                __nv_bfloat16 h2 = __float2bfloat16(v2), h3 = __float2bfloat16(v3);
                uint32_t hp0 = ((uint32_t)__bfloat16_as_ushort(h1) << 16) | __bfloat16_as_ushort(h0);
                uint32_t hp1 = ((uint32_t)__bfloat16_as_ushort(h3) << 16) | __bfloat16_as_ushort(h2);
                uint32_t lp0 = packbf(v0 - __bfloat162float(h0), v1 - __bfloat162float(h1));
                uint32_t lp1 = packbf(v2 - __bfloat162float(h2), v3 - __bfloat162float(h3));
                *(uint32_t*)(Chi + (size_t)row * Nd + col)       = hp0;
                *(uint32_t*)(Chi + (size_t)(row + 8) * Nd + col) = hp1;
                *(uint32_t*)(Clo + (size_t)row * Nd + col)       = lp0;
                *(uint32_t*)(Clo + (size_t)(row + 8) * Nd + col) = lp1;
            } else {
                float2 o0, o1;
                o0.x = v0; o0.y = v1;
                o1.x = v2; o1.y = v3;
                *(float2*)&Cf[(size_t)row * Nd + col]       = o0;
                *(float2*)&Cf[(size_t)(row + 8) * Nd + col] = o1;
            }
        }
    }
}

// ---------------------------------------------------------------------------
// Tensor-core causal flash attention (bf16 split HMMA), cp.async 3-buffer KV.
// 128-q tile, 8 warps x 16 rows. Writes y in triple-split [hi|lo|hi].
// ---------------------------------------------------------------------------
#define SQH_  0
#define SQL_  (128 * 144)            // 18432
#define SKV0_ (2 * 128 * 144)        // 36864
#define KVBUF_ (4 * 64 * 144)        // 36864 (KH, KL, VH, VL)
#define ATTN_SMEM (SKV0_ + 3 * KVBUF_)   // 147456

__global__ void __launch_bounds__(256, 1)
attn_mma(const __nv_bfloat16* __restrict__ qh_g, const __nv_bfloat16* __restrict__ ql_g,
         __nv_bfloat16* __restrict__ y2)
{
    extern __shared__ char sm[];
    const uint32_t base = smem_u32(sm);
    const int tid  = threadIdx.x;
    const int lane = tid & 31;
    const int wid  = tid >> 5;
    const int qt   = (int)gridDim.x - 1 - (int)blockIdx.x;   // long blocks first
    const int bh   = blockIdx.y;
    const int bb   = bh >> 4;
    const int h    = bh & 15;
    const int qbase = qt * 128;

    const int nkt = 2 * qt + 2;
    const int kr  = tid >> 2;
    const int kc4 = (tid & 3) * 2;

    // KV tile loader via cp.async (8 x 16B per thread)
    auto kv_load = [&](int jt, int s) {
        const uint32_t kb = base + SKV0_ + s * KVBUF_;
        const size_t ro = (size_t)(bb * T_ + jt * 64 + kr) * 3072 + 1024 + h * 64 + kc4 * 8;
        const __nv_bfloat16* ph = qh_g + ro;
        const __nv_bfloat16* pl = ql_g + ro;
        const uint32_t d = kb + kr * 144 + kc4 * 16;
        cp16(d,              ph);
        cp16(d + 16,         ph + 8);
        cp16(d + 9216,       pl);
        cp16(d + 9216 + 16,  pl + 8);
        cp16(d + 18432,      ph + 1024);
        cp16(d + 18432 + 16, ph + 1024 + 8);
        cp16(d + 27648,      pl + 1024);
        cp16(d + 27648 + 16, pl + 1024 + 8);
    };

    // preload KV stages 0,1
    kv_load(0, 0); CP_COMMIT();
    kv_load(1, 1); CP_COMMIT();

    // ---- load Q tile hi/lo into smem ----
    {
        const int r  = tid >> 1;
        const int c0 = (tid & 1) * 4;
        const size_t ro = ((size_t)(bb * T_ + qbase + r)) * 3072 + h * 64;
        const uint4* sh = (const uint4*)(qh_g + ro) + c0;
        const uint4* sl = (const uint4*)(ql_g + ro) + c0;
        #pragma unroll
        for (int c = 0; c < 4; ++c) {
            *(uint4*)(sm + SQH_ + r * 144 + (c0 + c) * 16) = sh[c];
            *(uint4*)(sm + SQL_ + r * 144 + (c0 + c) * 16) = sl[c];
        }
    }
    __syncthreads();

    // ---- Q fragments resident in registers ----
    const uint32_t aoff = (uint32_t)((wid * 16 + (lane & 15)) * 144 + (lane >> 4) * 16);
    uint32_t qhf[4][4], qlf[4][4];
    #pragma unroll
    for (int kc = 0; kc < 4; ++kc) {
        ldsm_x4(qhf[kc], base + SQH_ + aoff + kc * 32);
        ldsm_x4(qlf[kc], base + SQL_ + aoff + kc * 32);
    }

    float mrow0 = -INFINITY, mrow1 = -INFINITY, lr0 = 0.0f, lr1 = 0.0f;
    float accO[8][4] = {};

    const int qwbase = qbase + wid * 16;
    const int r0g = qwbase + (lane >> 2);
    const float sc = 0.125f;   // 1/sqrt(64)

    for (int j = 0; j < nkt; ++j) {
        const int kbase = j * 64;
        if (j + 1 < nkt) { CP_WAIT1(); } else { CP_WAIT0(); }
        __syncthreads();
        if (j + 2 < nkt) { kv_load(j + 2, (j + 2) % 3); CP_COMMIT(); }

        if (kbase <= qwbase + 15) {   // per-warp causal skip
            const uint32_t kvb = base + SKV0_ + (j % 3) * KVBUF_;

            // ---- S = Q K^T (3-term split) ----
            float sa[8][4];
            #pragma unroll
            for (int nt = 0; nt < 8; ++nt)
                #pragma unroll
                for (int i = 0; i < 4; ++i) sa[nt][i] = 0.0f;

            #pragma unroll
            for (int kc = 0; kc < 4; ++kc) {
                #pragma unroll
                for (int p = 0; p < 4; ++p) {
                    const uint32_t bo = (uint32_t)((p * 16 + (lane & 7) + ((lane >> 4) & 1) * 8) * 144
                                                   + ((lane >> 3) & 1) * 16 + kc * 32);
                    uint32_t kh[4], kl[4];
                    ldsm_x4(kh, kvb + bo);
                    ldsm_x4(kl, kvb + 9216 + bo);
                    mma_bf16(sa[2 * p],     qhf[kc], kh[0], kh[1]);
                    mma_bf16(sa[2 * p + 1], qhf[kc], kh[2], kh[3]);
                    mma_bf16(sa[2 * p],     qlf[kc], kh[0], kh[1]);
                    mma_bf16(sa[2 * p + 1], qlf[kc], kh[2], kh[3]);
                    mma_bf16(sa[2 * p],     qhf[kc], kl[0], kl[1]);
                    mma_bf16(sa[2 * p + 1], qhf[kc], kl[2], kl[3]);
                }
            }

            // ---- online softmax ----
            const bool diag = (kbase + 63 > qwbase);
            float mx0 = -INFINITY, mx1 = -INFINITY;
            #pragma unroll
            for (int nt = 0; nt < 8; ++nt) {
                const int col = kbase + nt * 8 + (lane & 3) * 2;
                float s0 = sa[nt][0] * sc, s1 = sa[nt][1] * sc;
                float s2 = sa[nt][2] * sc, s3 = sa[nt][3] * sc;
                if (diag) {
                    if (col     > r0g)     s0 = -INFINITY;
                    if (col + 1 > r0g)     s1 = -INFINITY;
                    if (col     > r0g + 8) s2 = -INFINITY;
                    if (col + 1 > r0g + 8) s3 = -INFINITY;
                }
                sa[nt][0] = s0; sa[nt][1] = s1; sa[nt][2] = s2; sa[nt][3] = s3;
                mx0 = fmaxf(mx0, fmaxf(s0, s1));
                mx1 = fmaxf(mx1, fmaxf(s2, s3));
            }
            mx0 = fmaxf(mx0, __shfl_xor_sync(0xffffffffu, mx0, 1));
            mx0 = fmaxf(mx0, __shfl_xor_sync(0xffffffffu, mx0, 2));
            mx1 = fmaxf(mx1, __shfl_xor_sync(0xffffffffu, mx1, 1));
            mx1 = fmaxf(mx1, __shfl_xor_sync(0xffffffffu, mx1, 2));

            const float mn0 = fmaxf(mrow0, mx0), mn1 = fmaxf(mrow1, mx1);
            const float f0 = __expf(mrow0 - mn0), f1 = __expf(mrow1 - mn1);
            mrow0 = mn0; mrow1 = mn1;

            float sum0 = 0.0f, sum1 = 0.0f;
            #pragma unroll
            for (int nt = 0; nt < 8; ++nt) {
                float p0 = __expf(sa[nt][0] - mn0);
                float p1 = __expf(sa[nt][1] - mn0);
                float p2 = __expf(sa[nt][2] - mn1);
                float p3 = __expf(sa[nt][3] - mn1);
                sa[nt][0] = p0; sa[nt][1] = p1; sa[nt][2] = p2; sa[nt][3] = p3;
                sum0 += p0 + p1;
                sum1 += p2 + p3;
            }
            sum0 += __shfl_xor_sync(0xffffffffu, sum0, 1);
            sum0 += __shfl_xor_sync(0xffffffffu, sum0, 2);
            sum1 += __shfl_xor_sync(0xffffffffu, sum1, 1);
            sum1 += __shfl_xor_sync(0xffffffffu, sum1, 2);
            lr0 = lr0 * f0 + sum0;
            lr1 = lr1 * f1 + sum1;
            #pragma unroll
            for (int nt = 0; nt < 8; ++nt) {
                accO[nt][0] *= f0; accO[nt][1] *= f0;
                accO[nt][2] *= f1; accO[nt][3] *= f1;
            }

            // ---- P -> A-fragments (register repack, exact hi/lo split) ----
            uint32_t phf[4][4], plf[4][4];
            #pragma unroll
            for (int kc = 0; kc < 4; ++kc) {
                #pragma unroll
                for (int half = 0; half < 2; ++half) {
                    const int nt = 2 * kc + half;
                    float v0 = sa[nt][0], v1 = sa[nt][1];
                    float v2 = sa[nt][2], v3 = sa[nt][3];
                    __nv_bfloat16 h0 = __float2bfloat16(v0), h1 = __float2bfloat16(v1);
                    __nv_bfloat16 h2 = __float2bfloat16(v2), h3 = __float2bfloat16(v3);
                    phf[kc][half * 2 + 0] = ((uint32_t)__bfloat16_as_ushort(h1) << 16)
                                            | __bfloat16_as_ushort(h0);
                    phf[kc][half * 2 + 1] = ((uint32_t)__bfloat16_as_ushort(h3) << 16)
                                            | __bfloat16_as_ushort(h2);
                    plf[kc][half * 2 + 0] = packbf(v0 - __bfloat162float(h0),
                                                   v1 - __bfloat162float(h1));
                    plf[kc][half * 2 + 1] = packbf(v2 - __bfloat162float(h2),
                                                   v3 - __bfloat162float(h3));
                }
            }

            // ---- accO += P V (3-term split, ldmatrix.trans on V) ----
            const uint32_t voff = (uint32_t)((lane & 15) * 144 + (lane >> 4) * 16);
            #pragma unroll
            for (int kc = 0; kc < 4; ++kc) {
                #pragma unroll
                for (int np = 0; np < 4; ++np) {
                    uint32_t vh[4], vl[4];
                    const uint32_t va = kvb + voff + kc * (16 * 144) + np * 32;
                    ldsm_x4_t(vh, va + 18432);
                    ldsm_x4_t(vl, va + 27648);
                    mma_bf16(accO[2 * np],     phf[kc], vh[0], vh[1]);
                    mma_bf16(accO[2 * np + 1], phf[kc], vh[2], vh[3]);
                    mma_bf16(accO[2 * np],     plf[kc], vh[0], vh[1]);
                    mma_bf16(accO[2 * np + 1], plf[kc], vh[2], vh[3]);
                    mma_bf16(accO[2 * np],     phf[kc], vl[0], vl[1]);
                    mma_bf16(accO[2 * np + 1], phf[kc], vl[2], vl[3]);
                }
            }
        }
    }

    // ---- epilogue: normalize, write triple-split [hi|lo|hi] to y2 ----
    const float inv0 = 1.0f / lr0, inv1 = 1.0f / lr1;
    const size_t row0 = (size_t)(bb * T_ + qwbase + (lane >> 2));
    const int colb = h * 64 + (lane & 3) * 2;
    #pragma unroll
    for (int nt = 0; nt < 8; ++nt) {
        const int col = colb + nt * 8;
        float v0 = accO[nt][0] * inv0, v1 = accO[nt][1] * inv0;
        float v2 = accO[nt][2] * inv1, v3 = accO[nt][3] * inv1;
        __nv_bfloat16 h0 = __float2bfloat16(v0), h1 = __float2bfloat16(v1);
        __nv_bfloat16 h2 = __float2bfloat16(v2), h3 = __float2bfloat16(v3);
        uint32_t hp0 = ((uint32_t)__bfloat16_as_ushort(h1) << 16) | __bfloat16_as_ushort(h0);
        uint32_t hp1 = ((uint32_t)__bfloat16_as_ushort(h3) << 16) | __bfloat16_as_ushort(h2);
        uint32_t lp0 = packbf(v0 - __bfloat162float(h0), v1 - __bfloat162float(h1));
        uint32_t lp1 = packbf(v2 - __bfloat162float(h2), v3 - __bfloat162float(h3));
        *(uint32_t*)(y2 + row0 * 3072 + col)              = hp0;
        *(uint32_t*)(y2 + row0 * 3072 + 1024 + col)       = lp0;
        *(uint32_t*)(y2 + row0 * 3072 + 2048 + col)       = hp0;
        *(uint32_t*)(y2 + (row0 + 8) * 3072 + col)        = hp1;
        *(uint32_t*)(y2 + (row0 + 8) * 3072 + 1024 + col) = lp1;
        *(uint32_t*)(y2 + (row0 + 8) * 3072 + 2048 + col) = hp1;
    }
}

// ---------------------------------------------------------------------------
// Launch
// ---------------------------------------------------------------------------
extern "C" void kernel_launch(void* const* d_in, const int* in_sizes, int n_in,
                              void* d_out, int out_size)
{
    (void)in_sizes; (void)n_in; (void)out_size;
    const float* x      = (const float*)d_in[0];
    const float* w_attn = (const float*)d_in[1];
    const float* b_attn = (const float*)d_in[2];
    const float* w_proj = (const float*)d_in[3];
    const float* b_proj = (const float*)d_in[4];
    float* out = (float*)d_out;

    __nv_bfloat16 *x2, *y2, *wa2, *wp2, *qkvh, *qkvl;
    cudaGetSymbolAddress((void**)&x2,   g_x2);
    cudaGetSymbolAddress((void**)&y2,   g_y2);
    cudaGetSymbolAddress((void**)&wa2,  g_wa2);
    cudaGetSymbolAddress((void**)&wp2,  g_wp2);
    cudaGetSymbolAddress((void**)&qkvh, g_qkvh);
    cudaGetSymbolAddress((void**)&qkvl, g_qkvl);

    cudaFuncSetAttribute(attn_mma, cudaFuncAttributeMaxDynamicSharedMemorySize,
                         ATTN_SMEM);
    cudaFuncSetAttribute(gemm_mma<1>, cudaFuncAttributeMaxDynamicSharedMemorySize,
                         GEMM_SMEM);
    cudaFuncSetAttribute(gemm_mma<0>, cudaFuncAttributeMaxDynamicSharedMemorySize,
                         GEMM_SMEM);

    // 1) snap weights -> bf16 triple [hi|hi|lo]
    zero_scales_kernel<<<1, 1>>>();
    maxabs_kernel<<<512, 256>>>((const float4*)w_attn, (N3C_ * C_) / 4, 0);
    maxabs_kernel<<<256, 256>>>((const float4*)w_proj, (C_ * C_) / 4, 1);
    snap_tc_kernel<<<768, 256>>>((const float4*)w_attn, wa2, (N3C_ * C_) / 4, 0);
    snap_tc_kernel<<<256, 256>>>((const float4*)w_proj, wp2, (C_ * C_) / 4, 1);

    // 2) x -> bf16 triple [hi|lo|hi]
    cvt_act_kernel<<<1024, 256>>>((const float4*)x, x2, (M_ * C_) / 4);

    // 3) qkv = x @ snap(w_attn)^T + b_attn  -> bf16 hi/lo
    gemm_mma<1><<<dim3(N3C_ / 128, M_ / 128), 256, GEMM_SMEM>>>(
        x2, wa2, b_attn, nullptr, qkvh, qkvl, N3C_);

    // 4) tensor-core causal flash attention -> y2 (triple split)
    attn_mma<<<dim3(T_ / 128, B_ * H_), 256, ATTN_SMEM>>>(qkvh, qkvl, y2);

    // 5) out = y @ snap(w_proj)^T + b_proj  (fp32 out)
    gemm_mma<0><<<dim3(C_ / 128, M_ / 128), 256, GEMM_SMEM>>>(
        y2, wp2, b_proj, out, nullptr, nullptr, C_);
}

// round 10
// speedup vs baseline: 1.2002x; 1.2002x over previous
#include <cuda_runtime.h>
#include <cuda_bf16.h>
#include <math.h>
#include <stdint.h>

// Problem constants
#define B_   2
#define T_   2048
#define C_   1024
#define H_   16
#define M_   (B_ * T_)      // 4096
#define N3C_ (3 * C_)       // 3072
#define KP_  (3 * C_)       // K' = 3*K (triple split)

// ---------------------------------------------------------------------------
// Helpers
// ---------------------------------------------------------------------------
__device__ __forceinline__ uint32_t smem_u32(const void* p) {
    uint32_t a;
    asm("{ .reg .u64 t; cvta.to.shared.u64 t, %1; cvt.u32.u64 %0, t; }"
        : "=r"(a) : "l"(p));
    return a;
}

__device__ __forceinline__ void ldsm_x4(uint32_t (&r)[4], uint32_t addr) {
    asm volatile("ldmatrix.sync.aligned.m8n8.x4.shared.b16 {%0,%1,%2,%3}, [%4];"
                 : "=r"(r[0]), "=r"(r[1]), "=r"(r[2]), "=r"(r[3]) : "r"(addr));
}

__device__ __forceinline__ void ldsm_x4_t(uint32_t (&r)[4], uint32_t addr) {
    asm volatile("ldmatrix.sync.aligned.m8n8.x4.trans.shared.b16 {%0,%1,%2,%3}, [%4];"
                 : "=r"(r[0]), "=r"(r[1]), "=r"(r[2]), "=r"(r[3]) : "r"(addr));
}

__device__ __forceinline__ void mma_bf16(float (&c)[4], const uint32_t (&a)[4],
                                         uint32_t b0, uint32_t b1) {
    asm volatile(
        "mma.sync.aligned.m16n8k16.row.col.f32.bf16.bf16.f32 "
        "{%0,%1,%2,%3}, {%4,%5,%6,%7}, {%8,%9}, {%0,%1,%2,%3};"
        : "+f"(c[0]), "+f"(c[1]), "+f"(c[2]), "+f"(c[3])
        : "r"(a[0]), "r"(a[1]), "r"(a[2]), "r"(a[3]), "r"(b0), "r"(b1));
}

__device__ __forceinline__ uint32_t packbf(float lo, float hi) {
    uint32_t u;
    asm("cvt.rn.bf16x2.f32 %0, %1, %2;" : "=r"(u) : "f"(hi), "f"(lo));
    return u;
}

// ---------------------------------------------------------------------------
// Scratch (device globals)
// ---------------------------------------------------------------------------
__device__ __nv_bfloat16 g_x2[(size_t)M_ * KP_];     // [Ah|Al|Ah] of x
__device__ __nv_bfloat16 g_y2[(size_t)M_ * KP_];     // [Ah|Al|Ah] of attn out
__device__ __nv_bfloat16 g_wa2[(size_t)N3C_ * KP_];  // [Bh|Bh|Bl] of snap(w_attn)
__device__ __nv_bfloat16 g_wp2[(size_t)C_ * KP_];    // [Bh|Bh|Bl] of snap(w_proj)
__device__ __nv_bfloat16 g_qkvh[(size_t)M_ * N3C_];  // qkv hi
__device__ __nv_bfloat16 g_qkvl[(size_t)M_ * N3C_];  // qkv lo
__device__ unsigned int g_maxbits[2];

// ---------------------------------------------------------------------------
// Snap + convert (vectorized; exact fp32 division to match reference buckets)
// ---------------------------------------------------------------------------
__global__ void zero_scales_kernel() { g_maxbits[0] = 0u; g_maxbits[1] = 0u; }

__global__ void __launch_bounds__(256) maxabs_kernel(const float4* __restrict__ w,
                                                     int n4, int slot) {
    float m = 0.0f;
    for (int i = blockIdx.x * blockDim.x + threadIdx.x; i < n4;
         i += gridDim.x * blockDim.x) {
        float4 v = w[i];
        m = fmaxf(m, fmaxf(fmaxf(fabsf(v.x), fabsf(v.y)),
                           fmaxf(fabsf(v.z), fabsf(v.w))));
    }
    #pragma unroll
    for (int o = 16; o > 0; o >>= 1)
        m = fmaxf(m, __shfl_xor_sync(0xffffffffu, m, o));
    __shared__ float sm[8];
    int lane = threadIdx.x & 31, wd = threadIdx.x >> 5;
    if (lane == 0) sm[wd] = m;
    __syncthreads();
    if (threadIdx.x < 8) {
        m = sm[threadIdx.x];
        #pragma unroll
        for (int o = 4; o > 0; o >>= 1)
            m = fmaxf(m, __shfl_xor_sync(0xffu, m, o));
        if (threadIdx.x == 0)
            atomicMax(&g_maxbits[slot], __float_as_uint(m));
    }
}

// nearest-LUT via midpoint thresholds (equivalent to argmin over the 16-entry LUT)
__device__ __forceinline__ float snapv(float wn) {
    float a = fabsf(wn);
    float v;
    if (a < 0.11688312f) {
        if (a < 0.03846150f) v = 0.0f;
        else v = (a < 0.08391600f) ? 0.076923f : 0.090909f;
    } else if (a < 0.26666650f) {
        v = (a < 0.17142850f) ? 0.142857f : 0.2f;
    } else if (a < 0.41666650f) {
        v = 0.333333f;
    } else {
        v = (a < 0.75f) ? 0.5f : 1.0f;
    }
    return copysignf(v, wn);
}

// snap weights -> triple [hi | hi | lo], vectorized x4, exact division
__global__ void __launch_bounds__(256) snap_tc_kernel(const float4* __restrict__ w,
                                                      __nv_bfloat16* __restrict__ out,
                                                      int n4, int slot) {
    const float scale = __uint_as_float(g_maxbits[slot]) + 1e-6f;
    for (int i = blockIdx.x * blockDim.x + threadIdx.x; i < n4;
         i += gridDim.x * blockDim.x) {
        float4 wv = w[i];
        float v0 = snapv(wv.x / scale) * scale;
        float v1 = snapv(wv.y / scale) * scale;
        float v2 = snapv(wv.z / scale) * scale;
        float v3 = snapv(wv.w / scale) * scale;
        __nv_bfloat16 h0 = __float2bfloat16(v0), h1 = __float2bfloat16(v1);
        __nv_bfloat16 h2 = __float2bfloat16(v2), h3 = __float2bfloat16(v3);
        uint32_t hp0 = ((uint32_t)__bfloat16_as_ushort(h1) << 16) | __bfloat16_as_ushort(h0);
        uint32_t hp1 = ((uint32_t)__bfloat16_as_ushort(h3) << 16) | __bfloat16_as_ushort(h2);
        uint32_t lp0 = packbf(v0 - __bfloat162float(h0), v1 - __bfloat162float(h1));
        uint32_t lp1 = packbf(v2 - __bfloat162float(h2), v3 - __bfloat162float(h3));
        int r = i >> 8, k = (i & 255) << 2;
        size_t base = (size_t)r * KP_;
        uint2 hp = make_uint2(hp0, hp1), lp = make_uint2(lp0, lp1);
        *(uint2*)(out + base + k)        = hp;
        *(uint2*)(out + base + 1024 + k) = hp;
        *(uint2*)(out + base + 2048 + k) = lp;
    }
}

// activations -> triple [hi | lo | hi], vectorized x4
__global__ void __launch_bounds__(256) cvt_act_kernel(const float4* __restrict__ a,
                                                      __nv_bfloat16* __restrict__ out,
                                                      int n4) {
    for (int i = blockIdx.x * blockDim.x + threadIdx.x; i < n4;
         i += gridDim.x * blockDim.x) {
        float4 v = a[i];
        __nv_bfloat16 h0 = __float2bfloat16(v.x), h1 = __float2bfloat16(v.y);
        __nv_bfloat16 h2 = __float2bfloat16(v.z), h3 = __float2bfloat16(v.w);
        uint32_t hp0 = ((uint32_t)__bfloat16_as_ushort(h1) << 16) | __bfloat16_as_ushort(h0);
        uint32_t hp1 = ((uint32_t)__bfloat16_as_ushort(h3) << 16) | __bfloat16_as_ushort(h2);
        uint32_t lp0 = packbf(v.x - __bfloat162float(h0), v.y - __bfloat162float(h1));
        uint32_t lp1 = packbf(v.z - __bfloat162float(h2), v.w - __bfloat162float(h3));
        int r = i >> 8, k = (i & 255) << 2;
        size_t base = (size_t)r * KP_;
        uint2 hp = make_uint2(hp0, hp1), lp = make_uint2(lp0, lp1);
        *(uint2*)(out + base + k)        = hp;
        *(uint2*)(out + base + 1024 + k) = lp;
        *(uint2*)(out + base + 2048 + k) = hp;
    }
}

// ---------------------------------------------------------------------------
// bf16 mma.sync GEMM (R7 verbatim): 128x128 tile, BK=32, 8 warps, reg staging,
// double-buffered static smem, occ 2. SPLIT=1: bf16 hi/lo out; SPLIT=0: fp32.
// ---------------------------------------------------------------------------
#define BK_      32
#define NITER_   (KP_ / BK_)    // 96
#define ASTR_    80

template <int SPLIT>
__global__ void __launch_bounds__(256, 2)
gemm_mma(const __nv_bfloat16* __restrict__ A2, const __nv_bfloat16* __restrict__ B2,
         const float* __restrict__ bias, float* __restrict__ Cf,
         __nv_bfloat16* __restrict__ Chi, __nv_bfloat16* __restrict__ Clo, int Nd)
{
    __shared__ __align__(16) char sA[2][128 * ASTR_];
    __shared__ __align__(16) char sB[2][128 * ASTR_];

    const int tid  = threadIdx.x;
    const int lane = tid & 31;
    const int wid  = tid >> 5;
    const int wm   = wid >> 2;
    const int wn   = wid & 3;
    const int m0   = blockIdx.y * 128;
    const int n0   = blockIdx.x * 128;

    const int r0  = tid >> 2;
    const int r1  = r0 + 64;
    const int seg = tid & 3;
    const uint4* gA0 = (const uint4*)(A2 + (size_t)(m0 + r0) * KP_) + seg;
    const uint4* gA1 = (const uint4*)(A2 + (size_t)(m0 + r1) * KP_) + seg;
    const uint4* gB0 = (const uint4*)(B2 + (size_t)(n0 + r0) * KP_) + seg;
    const uint4* gB1 = (const uint4*)(B2 + (size_t)(n0 + r1) * KP_) + seg;
    const int so0 = r0 * ASTR_ + seg * 16;
    const int so1 = r1 * ASTR_ + seg * 16;

    const uint32_t baseA0 = smem_u32(sA[0]);
    const uint32_t baseA1 = smem_u32(sA[1]);
    const uint32_t baseB0 = smem_u32(sB[0]);
    const uint32_t baseB1 = smem_u32(sB[1]);
    const uint32_t aoff = (uint32_t)((wm * 64 + (lane & 15)) * ASTR_ + (lane >> 4) * 16);
    const uint32_t boff = (uint32_t)((wn * 32 + (lane & 7) + ((lane >> 4) & 1) * 8) * ASTR_
                                     + ((lane >> 3) & 1) * 16);

    float acc[4][4][4] = {};

    uint4 ra0 = gA0[0], ra1 = gA1[0], rb0 = gB0[0], rb1 = gB1[0];
    *(uint4*)(sA[0] + so0) = ra0; *(uint4*)(sA[0] + so1) = ra1;
    *(uint4*)(sB[0] + so0) = rb0; *(uint4*)(sB[0] + so1) = rb1;
    __syncthreads();

    for (int it = 0; it < NITER_; ++it) {
        if (it + 1 < NITER_) {
            const int g = (it + 1) * 4;
            ra0 = gA0[g]; ra1 = gA1[g];
            rb0 = gB0[g]; rb1 = gB1[g];
        }
        const uint32_t bA = (it & 1) ? baseA1 : baseA0;
        const uint32_t bB = (it & 1) ? baseB1 : baseB0;

        #pragma unroll
        for (int ks = 0; ks < 2; ++ks) {
            uint32_t af[4][4];
            #pragma unroll
            for (int mt = 0; mt < 4; ++mt)
                ldsm_x4(af[mt], bA + aoff + mt * (16 * ASTR_) + ks * 32);
            #pragma unroll
            for (int p = 0; p < 2; ++p) {
                uint32_t bf[4];
                ldsm_x4(bf, bB + boff + p * (16 * ASTR_) + ks * 32);
                #pragma unroll
                for (int mt = 0; mt < 4; ++mt) {
                    mma_bf16(acc[mt][2 * p],     af[mt], bf[0], bf[1]);
                    mma_bf16(acc[mt][2 * p + 1], af[mt], bf[2], bf[3]);
                }
            }
        }

        if (it + 1 < NITER_) {
            char* dA = sA[(it + 1) & 1];
            char* dB = sB[(it + 1) & 1];
            *(uint4*)(dA + so0) = ra0; *(uint4*)(dA + so1) = ra1;
            *(uint4*)(dB + so0) = rb0; *(uint4*)(dB + so1) = rb1;
        }
        __syncthreads();
    }

    #pragma unroll
    for (int nt = 0; nt < 4; ++nt) {
        const int col = n0 + wn * 32 + nt * 8 + (lane & 3) * 2;
        const float bv0 = bias[col];
        const float bv1 = bias[col + 1];
        #pragma unroll
        for (int mt = 0; mt < 4; ++mt) {
            const int row = m0 + wm * 64 + mt * 16 + (lane >> 2);
            float v0 = acc[mt][nt][0] + bv0, v1 = acc[mt][nt][1] + bv1;
            float v2 = acc[mt][nt][2] + bv0, v3 = acc[mt][nt][3] + bv1;
            if (SPLIT) {
                __nv_bfloat16 h0 = __float2bfloat16(v0), h1 = __float2bfloat16(v1);
                __nv_bfloat16 h2 = __float2bfloat16(v2), h3 = __float2bfloat16(v3);
                uint32_t hp0 = ((uint32_t)__bfloat16_as_ushort(h1) << 16) | __bfloat16_as_ushort(h0);
                uint32_t hp1 = ((uint32_t)__bfloat16_as_ushort(h3) << 16) | __bfloat16_as_ushort(h2);
                uint32_t lp0 = packbf(v0 - __bfloat162float(h0), v1 - __bfloat162float(h1));
                uint32_t lp1 = packbf(v2 - __bfloat162float(h2), v3 - __bfloat162float(h3));
                *(uint32_t*)(Chi + (size_t)row * Nd + col)       = hp0;
                *(uint32_t*)(Chi + (size_t)(row + 8) * Nd + col) = hp1;
                *(uint32_t*)(Clo + (size_t)row * Nd + col)       = lp0;
                *(uint32_t*)(Clo + (size_t)(row + 8) * Nd + col) = lp1;
            } else {
                float2 o0, o1;
                o0.x = v0; o0.y = v1;
                o1.x = v2; o1.y = v3;
                *(float2*)&Cf[(size_t)row * Nd + col]       = o0;
                *(float2*)&Cf[(size_t)(row + 8) * Nd + col] = o1;
            }
        }
    }
}

// ---------------------------------------------------------------------------
// Tensor-core causal flash attention (R7 verbatim): bf16 split HMMA,
// 128-q tile, 8 warps x 16 rows, 64-key tiles double-buffered, occ 2.
// Writes y directly in triple-split layout [hi|lo|hi] into g_y2.
// ---------------------------------------------------------------------------
#define SQH_  0
#define SQL_  (128 * 144)            // 18432
#define SKV0_ (2 * 128 * 144)        // 36864
#define KVBUF_ (4 * 64 * 144)        // 36864 (KH, KL, VH, VL)
#define ATTN_SMEM (SKV0_ + 2 * KVBUF_)   // 110592

__global__ void __launch_bounds__(256, 1)
attn_mma(const __nv_bfloat16* __restrict__ qh_g, const __nv_bfloat16* __restrict__ ql_g,
         __nv_bfloat16* __restrict__ y2)
{
    extern __shared__ char sm[];
    const uint32_t base = smem_u32(sm);
    const int tid  = threadIdx.x;
    const int lane = tid & 31;
    const int wid  = tid >> 5;
    const int qt   = (int)gridDim.x - 1 - (int)blockIdx.x;   // long blocks first
    const int bh   = blockIdx.y;
    const int bb   = bh >> 4;
    const int h    = bh & 15;
    const int qbase = qt * 128;

    // ---- load Q tile hi/lo into smem ----
    {
        const int r  = tid >> 1;
        const int c0 = (tid & 1) * 4;
        const size_t ro = ((size_t)(bb * T_ + qbase + r)) * 3072 + h * 64;
        const uint4* sh = (const uint4*)(qh_g + ro) + c0;
        const uint4* sl = (const uint4*)(ql_g + ro) + c0;
        #pragma unroll
        for (int c = 0; c < 4; ++c) {
            *(uint4*)(sm + SQH_ + r * 144 + (c0 + c) * 16) = sh[c];
            *(uint4*)(sm + SQL_ + r * 144 + (c0 + c) * 16) = sl[c];
        }
    }
    __syncthreads();

    // ---- Q fragments resident in registers for all k tiles ----
    const uint32_t aoff = (uint32_t)((wid * 16 + (lane & 15)) * 144 + (lane >> 4) * 16);
    uint32_t qhf[4][4], qlf[4][4];
    #pragma unroll
    for (int kc = 0; kc < 4; ++kc) {
        ldsm_x4(qhf[kc], base + SQH_ + aoff + kc * 32);
        ldsm_x4(qlf[kc], base + SQL_ + aoff + kc * 32);
    }

    // KV loader mapping: 64 rows x 8 uint4, 256 threads -> 2 uint4/thread/subtile
    const int kr  = tid >> 2;
    const int kc4 = (tid & 3) * 2;
    const int ckq = (1024 + h * 64) >> 3;
    const int cvq = (2048 + h * 64) >> 3;

    float mrow0 = -INFINITY, mrow1 = -INFINITY, lr0 = 0.0f, lr1 = 0.0f;
    float accO[8][4] = {};

    const int nkt = 2 * qt + 2;
    const int qwbase = qbase + wid * 16;
    const int r0g = qwbase + (lane >> 2);
    const float sc = 0.125f;   // 1/sqrt(64)

    uint4 stage[8];
    // load + store tile 0
    {
        const size_t ro = ((size_t)(bb * T_ + kr)) * 3072;
        const uint4* ph = (const uint4*)(qh_g + ro);
        const uint4* pl = (const uint4*)(ql_g + ro);
        stage[0] = ph[ckq + kc4]; stage[1] = ph[ckq + kc4 + 1];
        stage[2] = pl[ckq + kc4]; stage[3] = pl[ckq + kc4 + 1];
        stage[4] = ph[cvq + kc4]; stage[5] = ph[cvq + kc4 + 1];
        stage[6] = pl[cvq + kc4]; stage[7] = pl[cvq + kc4 + 1];
        char* d = sm + SKV0_ + kr * 144 + kc4 * 16;
        *(uint4*)(d)             = stage[0]; *(uint4*)(d + 16)         = stage[1];
        *(uint4*)(d + 9216)      = stage[2]; *(uint4*)(d + 9216 + 16)  = stage[3];
        *(uint4*)(d + 18432)     = stage[4]; *(uint4*)(d + 18432 + 16) = stage[5];
        *(uint4*)(d + 27648)     = stage[6]; *(uint4*)(d + 27648 + 16) = stage[7];
    }
    __syncthreads();

    for (int j = 0; j < nkt; ++j) {
        const int buf = j & 1;
        const int kbase = j * 64;

        if (j + 1 < nkt) {   // prefetch next tile into registers
            const size_t ro = ((size_t)(bb * T_ + (j + 1) * 64 + kr)) * 3072;
            const uint4* ph = (const uint4*)(qh_g + ro);
            const uint4* pl = (const uint4*)(ql_g + ro);
            stage[0] = ph[ckq + kc4]; stage[1] = ph[ckq + kc4 + 1];
            stage[2] = pl[ckq + kc4]; stage[3] = pl[ckq + kc4 + 1];
            stage[4] = ph[cvq + kc4]; stage[5] = ph[cvq + kc4 + 1];
            stage[6] = pl[cvq + kc4]; stage[7] = pl[cvq + kc4 + 1];
        }

        if (kbase <= qwbase + 15) {   // per-warp causal skip
            const uint32_t kvb = base + SKV0_ + buf * KVBUF_;

            // ---- S = Q K^T (3-term split) ----
            float sa[8][4];
            #pragma unroll
            for (int nt = 0; nt < 8; ++nt)
                #pragma unroll
                for (int i = 0; i < 4; ++i) sa[nt][i] = 0.0f;

            #pragma unroll
            for (int kc = 0; kc < 4; ++kc) {
                #pragma unroll
                for (int p = 0; p < 4; ++p) {
                    const uint32_t bo = (uint32_t)((p * 16 + (lane & 7) + ((lane >> 4) & 1) * 8) * 144
                                                   + ((lane >> 3) & 1) * 16 + kc * 32);
                    uint32_t kh[4], kl[4];
                    ldsm_x4(kh, kvb + bo);
                    ldsm_x4(kl, kvb + 9216 + bo);
                    mma_bf16(sa[2 * p],     qhf[kc], kh[0], kh[1]);
                    mma_bf16(sa[2 * p + 1], qhf[kc], kh[2], kh[3]);
                    mma_bf16(sa[2 * p],     qlf[kc], kh[0], kh[1]);
                    mma_bf16(sa[2 * p + 1], qlf[kc], kh[2], kh[3]);
                    mma_bf16(sa[2 * p],     qhf[kc], kl[0], kl[1]);
                    mma_bf16(sa[2 * p + 1], qhf[kc], kl[2], kl[3]);
                }
            }

            // ---- online softmax ----
            const bool diag = (kbase + 63 > qwbase);
            float mx0 = -INFINITY, mx1 = -INFINITY;
            #pragma unroll
            for (int nt = 0; nt < 8; ++nt) {
                const int col = kbase + nt * 8 + (lane & 3) * 2;
                float s0 = sa[nt][0] * sc, s1 = sa[nt][1] * sc;
                float s2 = sa[nt][2] * sc, s3 = sa[nt][3] * sc;
                if (diag) {
                    if (col     > r0g)     s0 = -INFINITY;
                    if (col + 1 > r0g)     s1 = -INFINITY;
                    if (col     > r0g + 8) s2 = -INFINITY;
                    if (col + 1 > r0g + 8) s3 = -INFINITY;
                }
                sa[nt][0] = s0; sa[nt][1] = s1; sa[nt][2] = s2; sa[nt][3] = s3;
                mx0 = fmaxf(mx0, fmaxf(s0, s1));
                mx1 = fmaxf(mx1, fmaxf(s2, s3));
            }
            mx0 = fmaxf(mx0, __shfl_xor_sync(0xffffffffu, mx0, 1));
            mx0 = fmaxf(mx0, __shfl_xor_sync(0xffffffffu, mx0, 2));
            mx1 = fmaxf(mx1, __shfl_xor_sync(0xffffffffu, mx1, 1));
            mx1 = fmaxf(mx1, __shfl_xor_sync(0xffffffffu, mx1, 2));

            const float mn0 = fmaxf(mrow0, mx0), mn1 = fmaxf(mrow1, mx1);
            const float f0 = __expf(mrow0 - mn0), f1 = __expf(mrow1 - mn1);
            mrow0 = mn0; mrow1 = mn1;

            float sum0 = 0.0f, sum1 = 0.0f;
            #pragma unroll
            for (int nt = 0; nt < 8; ++nt) {
                float p0 = __expf(sa[nt][0] - mn0);
                float p1 = __expf(sa[nt][1] - mn0);
                float p2 = __expf(sa[nt][2] - mn1);
                float p3 = __expf(sa[nt][3] - mn1);
                sa[nt][0] = p0; sa[nt][1] = p1; sa[nt][2] = p2; sa[nt][3] = p3;
                sum0 += p0 + p1;
                sum1 += p2 + p3;
            }
            sum0 += __shfl_xor_sync(0xffffffffu, sum0, 1);
            sum0 += __shfl_xor_sync(0xffffffffu, sum0, 2);
            sum1 += __shfl_xor_sync(0xffffffffu, sum1, 1);
            sum1 += __shfl_xor_sync(0xffffffffu, sum1, 2);
            lr0 = lr0 * f0 + sum0;
            lr1 = lr1 * f1 + sum1;
            #pragma unroll
            for (int nt = 0; nt < 8; ++nt) {
                accO[nt][0] *= f0; accO[nt][1] *= f0;
                accO[nt][2] *= f1; accO[nt][3] *= f1;
            }

            // ---- P -> A-fragments (register repack, exact hi/lo split) ----
            uint32_t phf[4][4], plf[4][4];
            #pragma unroll
            for (int kc = 0; kc < 4; ++kc) {
                #pragma unroll
                for (int half = 0; half < 2; ++half) {
                    const int nt = 2 * kc + half;
                    float v0 = sa[nt][0], v1 = sa[nt][1];
                    float v2 = sa[nt][2], v3 = sa[nt][3];
                    __nv_bfloat16 h0 = __float2bfloat16(v0), h1 = __float2bfloat16(v1);
                    __nv_bfloat16 h2 = __float2bfloat16(v2), h3 = __float2bfloat16(v3);
                    phf[kc][half * 2 + 0] = ((uint32_t)__bfloat16_as_ushort(h1) << 16)
                                            | __bfloat16_as_ushort(h0);
                    phf[kc][half * 2 + 1] = ((uint32_t)__bfloat16_as_ushort(h3) << 16)
                                            | __bfloat16_as_ushort(h2);
                    plf[kc][half * 2 + 0] = packbf(v0 - __bfloat162float(h0),
                                                   v1 - __bfloat162float(h1));
                    plf[kc][half * 2 + 1] = packbf(v2 - __bfloat162float(h2),
                                                   v3 - __bfloat162float(h3));
                }
            }

            // ---- accO += P V (3-term split, ldmatrix.trans on V) ----
            const uint32_t voff = (uint32_t)((lane & 15) * 144 + (lane >> 4) * 16);
            #pragma unroll
            for (int kc = 0; kc < 4; ++kc) {
                #pragma unroll
                for (int np = 0; np < 4; ++np) {
                    uint32_t vh[4], vl[4];
                    const uint32_t va = kvb + voff + kc * (16 * 144) + np * 32;
                    ldsm_x4_t(vh, va + 18432);
                    ldsm_x4_t(vl, va + 27648);
                    mma_bf16(accO[2 * np],     phf[kc], vh[0], vh[1]);
                    mma_bf16(accO[2 * np + 1], phf[kc], vh[2], vh[3]);
                    mma_bf16(accO[2 * np],     plf[kc], vh[0], vh[1]);
                    mma_bf16(accO[2 * np + 1], plf[kc], vh[2], vh[3]);
                    mma_bf16(accO[2 * np],     phf[kc], vl[0], vl[1]);
                    mma_bf16(accO[2 * np + 1], phf[kc], vl[2], vl[3]);
                }
            }
        }

        if (j + 1 < nkt) {   // store prefetched tile into the other buffer
            char* d = sm + SKV0_ + (1 - buf) * KVBUF_ + kr * 144 + kc4 * 16;
            *(uint4*)(d)             = stage[0]; *(uint4*)(d + 16)         = stage[1];
            *(uint4*)(d + 9216)      = stage[2]; *(uint4*)(d + 9216 + 16)  = stage[3];
            *(uint4*)(d + 18432)     = stage[4]; *(uint4*)(d + 18432 + 16) = stage[5];
            *(uint4*)(d + 27648)     = stage[6]; *(uint4*)(d + 27648 + 16) = stage[7];
        }
        __syncthreads();
    }

    // ---- epilogue: normalize, write triple-split [hi|lo|hi] to y2 ----
    const float inv0 = 1.0f / lr0, inv1 = 1.0f / lr1;
    const size_t row0 = (size_t)(bb * T_ + qwbase + (lane >> 2));
    const int colb = h * 64 + (lane & 3) * 2;
    #pragma unroll
    for (int nt = 0; nt < 8; ++nt) {
        const int col = colb + nt * 8;
        float v0 = accO[nt][0] * inv0, v1 = accO[nt][1] * inv0;
        float v2 = accO[nt][2] * inv1, v3 = accO[nt][3] * inv1;
        __nv_bfloat16 h0 = __float2bfloat16(v0), h1 = __float2bfloat16(v1);
        __nv_bfloat16 h2 = __float2bfloat16(v2), h3 = __float2bfloat16(v3);
        uint32_t hp0 = ((uint32_t)__bfloat16_as_ushort(h1) << 16) | __bfloat16_as_ushort(h0);
        uint32_t hp1 = ((uint32_t)__bfloat16_as_ushort(h3) << 16) | __bfloat16_as_ushort(h2);
        uint32_t lp0 = packbf(v0 - __bfloat162float(h0), v1 - __bfloat162float(h1));
        uint32_t lp1 = packbf(v2 - __bfloat162float(h2), v3 - __bfloat162float(h3));
        *(uint32_t*)(y2 + row0 * 3072 + col)              = hp0;
        *(uint32_t*)(y2 + row0 * 3072 + 1024 + col)       = lp0;
        *(uint32_t*)(y2 + row0 * 3072 + 2048 + col)       = hp0;
        *(uint32_t*)(y2 + (row0 + 8) * 3072 + col)        = hp1;
        *(uint32_t*)(y2 + (row0 + 8) * 3072 + 1024 + col) = lp1;
        *(uint32_t*)(y2 + (row0 + 8) * 3072 + 2048 + col) = hp1;
    }
}

// ---------------------------------------------------------------------------
// Launch
// ---------------------------------------------------------------------------
extern "C" void kernel_launch(void* const* d_in, const int* in_sizes, int n_in,
                              void* d_out, int out_size)
{
    (void)in_sizes; (void)n_in; (void)out_size;
    const float* x      = (const float*)d_in[0];
    const float* w_attn = (const float*)d_in[1];
    const float* b_attn = (const float*)d_in[2];
    const float* w_proj = (const float*)d_in[3];
    const float* b_proj = (const float*)d_in[4];
    float* out = (float*)d_out;

    __nv_bfloat16 *x2, *y2, *wa2, *wp2, *qkvh, *qkvl;
    cudaGetSymbolAddress((void**)&x2,   g_x2);
    cudaGetSymbolAddress((void**)&y2,   g_y2);
    cudaGetSymbolAddress((void**)&wa2,  g_wa2);
    cudaGetSymbolAddress((void**)&wp2,  g_wp2);
    cudaGetSymbolAddress((void**)&qkvh, g_qkvh);
    cudaGetSymbolAddress((void**)&qkvl, g_qkvl);

    cudaFuncSetAttribute(attn_mma, cudaFuncAttributeMaxDynamicSharedMemorySize,
                         ATTN_SMEM);

    // 1) snap weights -> bf16 triple [hi|hi|lo]
    zero_scales_kernel<<<1, 1>>>();
    maxabs_kernel<<<512, 256>>>((const float4*)w_attn, (N3C_ * C_) / 4, 0);
    maxabs_kernel<<<256, 256>>>((const float4*)w_proj, (C_ * C_) / 4, 1);
    snap_tc_kernel<<<768, 256>>>((const float4*)w_attn, wa2, (N3C_ * C_) / 4, 0);
    snap_tc_kernel<<<256, 256>>>((const float4*)w_proj, wp2, (C_ * C_) / 4, 1);

    // 2) x -> bf16 triple [hi|lo|hi]
    cvt_act_kernel<<<1024, 256>>>((const float4*)x, x2, (M_ * C_) / 4);

    // 3) qkv = x @ snap(w_attn)^T + b_attn  -> bf16 hi/lo
    gemm_mma<1><<<dim3(N3C_ / 128, M_ / 128), 256>>>(
        x2, wa2, b_attn, nullptr, qkvh, qkvl, N3C_);

    // 4) tensor-core causal flash attention -> y2 (triple split)
    attn_mma<<<dim3(T_ / 128, B_ * H_), 256, ATTN_SMEM>>>(qkvh, qkvl, y2);

    // 5) out = y @ snap(w_proj)^T + b_proj  (fp32 out)
    gemm_mma<0><<<dim3(C_ / 128, M_ / 128), 256>>>(
        y2, wp2, b_proj, out, nullptr, nullptr, C_);
}